// round 3
// baseline (speedup 1.0000x reference)
#include <cuda_runtime.h>
#include <cuda_bf16.h>
#include <cstdint>
#include <cstddef>

// ---------------------------------------------------------------------------
// Problem constants
// ---------------------------------------------------------------------------
#define N_ATOM  100000
#define N_BOND  200000
#define N_MOTIF 50000
#define N_CELL  5000
#define H 64
#define N_LAYERS 3

#define MAX_ROWS 200000   // max rows among node types (bond)

// ---------------------------------------------------------------------------
// Scratch (static device allocations only; no cudaMalloc anywhere)
// ---------------------------------------------------------------------------
__device__ __align__(16) float g_cur_atom [N_ATOM  * H];
__device__ __align__(16) float g_cur_bond [N_BOND  * H];
__device__ __align__(16) float g_cur_motif[N_MOTIF * H];
__device__ __align__(16) float g_cur_cell [N_CELL  * H];
__device__ __align__(16) float g_acc_atom [N_ATOM  * H];
__device__ __align__(16) float g_acc_bond [N_BOND  * H];
__device__ __align__(16) float g_acc_motif[N_MOTIF * H];
__device__ __align__(16) float g_acc_cell [N_CELL  * H];
__device__ __align__(16) float g_y        [MAX_ROWS * H];   // transformed src feats
__device__ __align__(16) float g_cnt      [MAX_ROWS];       // per-dst degree -> inv
__device__ __align__(16) float g_WrSum    [N_LAYERS * 4 * H * H];
__device__ __align__(16) float g_blSum    [N_LAYERS * 4 * H];

// ---------------------------------------------------------------------------
// Small utility kernels
// ---------------------------------------------------------------------------
__global__ void copy_k(float* __restrict__ dst, const float* __restrict__ src, size_t n) {
    size_t i = (size_t)blockIdx.x * blockDim.x + threadIdx.x;
    size_t stride = (size_t)gridDim.x * blockDim.x;
    for (; i < n; i += stride) dst[i] = src[i];
}

__global__ void zero_k(float* __restrict__ p, int n) {
    int i = blockIdx.x * blockDim.x + threadIdx.x;
    if (i < n) p[i] = 0.0f;
}

__global__ void relu_k(float* __restrict__ dst, const float* __restrict__ src, size_t n) {
    size_t i = (size_t)blockIdx.x * blockDim.x + threadIdx.x;
    size_t stride = (size_t)gridDim.x * blockDim.x;
    for (; i < n; i += stride) dst[i] = fmaxf(src[i], 0.0f);
}

__global__ void inv_k(float* __restrict__ cnt, int n) {
    int i = blockIdx.x * blockDim.x + threadIdx.x;
    if (i < n) cnt[i] = 1.0f / fmaxf(cnt[i], 1.0f);
}

// Sum Wr over relations targeting each dst type: WrSum[l][t][64][64]
__global__ void wrsum_k(const float* __restrict__ Wr, float* __restrict__ WrSum) {
    int i = blockIdx.x * blockDim.x + threadIdx.x;
    if (i >= N_LAYERS * 4 * H * H) return;
    int l = i / (4 * H * H);
    int rem = i - l * 4 * H * H;
    int t = rem >> 12;          // / 4096
    int e = rem & 4095;
    const int rcnt[4]     = {1, 2, 3, 3};
    const int rlist[4][3] = {{0,0,0},{1,3,0},{2,4,5},{6,7,8}};
    float s = 0.0f;
    for (int j = 0; j < rcnt[t]; j++)
        s += Wr[((size_t)l * 9 + rlist[t][j]) * (H * H) + e];
    WrSum[i] = s;
}

__global__ void blsum_k(const float* __restrict__ bl, float* __restrict__ blSum) {
    int i = blockIdx.x * blockDim.x + threadIdx.x;
    if (i >= N_LAYERS * 4 * H) return;
    int l = i / (4 * H);
    int rem = i - l * 4 * H;
    int t = rem >> 6;
    int e = rem & 63;
    const int rcnt[4]     = {1, 2, 3, 3};
    const int rlist[4][3] = {{0,0,0},{1,3,0},{2,4,5},{6,7,8}};
    float s = 0.0f;
    for (int j = 0; j < rcnt[t]; j++)
        s += bl[((size_t)l * 9 + rlist[t][j]) * H + e];
    blSum[i] = s;
}

// ---------------------------------------------------------------------------
// Row-GEMM: Y[row] = X[row] @ W (+ bias).  W is [64][64] row-major (k-major).
// One warp per row; W staged in shared memory; shfl-broadcast of inputs.
// ---------------------------------------------------------------------------
__global__ void gemm64_k(const float* __restrict__ X, const float* __restrict__ W,
                         const float* __restrict__ bias, float* __restrict__ Y, int n) {
    __shared__ float Ws[H * H];
    for (int i = threadIdx.x; i < H * H; i += blockDim.x) Ws[i] = W[i];
    __syncthreads();

    int warp = threadIdx.x >> 5;
    int lane = threadIdx.x & 31;
    int row  = blockIdx.x * (blockDim.x >> 5) + warp;
    if (row >= n) return;

    const float* x = X + (size_t)row * H;
    float in_lo = x[lane];
    float in_hi = x[lane + 32];
    float a0 = bias ? bias[lane]      : 0.0f;
    float a1 = bias ? bias[lane + 32] : 0.0f;

#pragma unroll
    for (int k = 0; k < 32; k++) {
        float a = __shfl_sync(0xffffffffu, in_lo, k);
        a0 += a * Ws[k * H + lane];
        a1 += a * Ws[k * H + lane + 32];
    }
#pragma unroll
    for (int k = 0; k < 32; k++) {
        float a = __shfl_sync(0xffffffffu, in_hi, k);
        a0 += a * Ws[(k + 32) * H + lane];
        a1 += a * Ws[(k + 32) * H + lane + 32];
    }
    Y[(size_t)row * H + lane]      = a0;
    Y[(size_t)row * H + lane + 32] = a1;
}

// ---------------------------------------------------------------------------
// Edge kernels.  NOTE: edge index tensors are int32 (JAX x64 disabled — the
// reference's astype(int64) silently yields int32).  Layout [2, E] row-major:
// ei[0..E) = src, ei[E..2E) = dst.
// ---------------------------------------------------------------------------
__global__ void count_k(const int* __restrict__ ei, int E, float* __restrict__ cnt) {
    int e = blockIdx.x * blockDim.x + threadIdx.x;
    if (e >= E) return;
    int dst = ei[E + e];
    atomicAdd(&cnt[dst], 1.0f);
}

// 16 threads per edge, each handles one float4 chunk of the 64-wide row.
// acc[dst] += y[src] * inv_cnt[dst]   via red.global.add.v4.f32
__global__ void scatter_k(const int* __restrict__ ei, int E,
                          const float* __restrict__ y,
                          const float* __restrict__ inv,
                          float* __restrict__ acc) {
    int gid = blockIdx.x * blockDim.x + threadIdx.x;
    int e = gid >> 4;
    int c = gid & 15;
    if (e >= E) return;
    int src = __ldg(&ei[e]);
    int dst = __ldg(&ei[E + e]);
    float w = __ldg(&inv[dst]);
    float4 v = *(const float4*)(y + (size_t)src * H + c * 4);
    v.x *= w; v.y *= w; v.z *= w; v.w *= w;
    float* p = acc + (size_t)dst * H + c * 4;
    asm volatile("red.global.add.v4.f32 [%0], {%1,%2,%3,%4};"
                 :: "l"(p), "f"(v.x), "f"(v.y), "f"(v.z), "f"(v.w)
                 : "memory");
}

// ---------------------------------------------------------------------------
// Head: out[row] = softplus(cell[row] @ projW + projb) @ outW + outb
// ---------------------------------------------------------------------------
__global__ void head_k(const float* __restrict__ X, const float* __restrict__ W,
                       const float* __restrict__ b, const float* __restrict__ ow,
                       const float* __restrict__ ob, float* __restrict__ out, int n) {
    __shared__ float Ws[H * H];
    for (int i = threadIdx.x; i < H * H; i += blockDim.x) Ws[i] = W[i];
    __syncthreads();

    int warp = threadIdx.x >> 5;
    int lane = threadIdx.x & 31;
    int row  = blockIdx.x * (blockDim.x >> 5) + warp;
    if (row >= n) return;

    const float* x = X + (size_t)row * H;
    float in_lo = x[lane];
    float in_hi = x[lane + 32];
    float a0 = b[lane];
    float a1 = b[lane + 32];

#pragma unroll
    for (int k = 0; k < 32; k++) {
        float a = __shfl_sync(0xffffffffu, in_lo, k);
        a0 += a * Ws[k * H + lane];
        a1 += a * Ws[k * H + lane + 32];
    }
#pragma unroll
    for (int k = 0; k < 32; k++) {
        float a = __shfl_sync(0xffffffffu, in_hi, k);
        a0 += a * Ws[(k + 32) * H + lane];
        a1 += a * Ws[(k + 32) * H + lane + 32];
    }
    // stable softplus: max(x,0) + log1p(exp(-|x|))
    a0 = fmaxf(a0, 0.0f) + log1pf(expf(-fabsf(a0)));
    a1 = fmaxf(a1, 0.0f) + log1pf(expf(-fabsf(a1)));
    float s = a0 * ow[lane] + a1 * ow[lane + 32];
#pragma unroll
    for (int o = 16; o > 0; o >>= 1) s += __shfl_down_sync(0xffffffffu, s, o);
    if (lane == 0) out[row] = s + ob[0];
}

// ---------------------------------------------------------------------------
// Host orchestration
// ---------------------------------------------------------------------------
extern "C" void kernel_launch(void* const* d_in, const int* in_sizes, int n_in,
                              void* d_out, int out_size) {
    // Input order (metadata): x_atom, x_bond, x_motif, x_cell, Wl, bl, Wr,
    // proj_W, proj_b, out_W, out_b, ei_aa..ei_mc (int32 [2,E] each)
    const float* x_in[4] = {(const float*)d_in[0], (const float*)d_in[1],
                            (const float*)d_in[2], (const float*)d_in[3]};
    const float* Wl    = (const float*)d_in[4];
    const float* bl    = (const float*)d_in[5];
    const float* Wr    = (const float*)d_in[6];
    const float* projW = (const float*)d_in[7];
    const float* projb = (const float*)d_in[8];
    const float* outW  = (const float*)d_in[9];
    const float* outb  = (const float*)d_in[10];

    const int* ei[9];
    int E[9];
    for (int r = 0; r < 9; r++) {
        ei[r] = (const int*)d_in[11 + r];
        E[r]  = in_sizes[11 + r] / 2;
    }

    const int NT[4] = {N_ATOM, N_BOND, N_MOTIF, N_CELL};
    const int st[9] = {0, 0, 0, 1, 1, 2, 0, 1, 2};
    const int dt[9] = {0, 1, 2, 1, 2, 2, 3, 3, 3};

    float *cur[4], *acc[4], *y, *cnt, *WrSum, *blSum;
    cudaGetSymbolAddress((void**)&cur[0], g_cur_atom);
    cudaGetSymbolAddress((void**)&cur[1], g_cur_bond);
    cudaGetSymbolAddress((void**)&cur[2], g_cur_motif);
    cudaGetSymbolAddress((void**)&cur[3], g_cur_cell);
    cudaGetSymbolAddress((void**)&acc[0], g_acc_atom);
    cudaGetSymbolAddress((void**)&acc[1], g_acc_bond);
    cudaGetSymbolAddress((void**)&acc[2], g_acc_motif);
    cudaGetSymbolAddress((void**)&acc[3], g_acc_cell);
    cudaGetSymbolAddress((void**)&y,     g_y);
    cudaGetSymbolAddress((void**)&cnt,   g_cnt);
    cudaGetSymbolAddress((void**)&WrSum, g_WrSum);
    cudaGetSymbolAddress((void**)&blSum, g_blSum);

    const int TB = 256;

    // 0. copy inputs into cur buffers
    for (int t = 0; t < 4; t++) {
        size_t n = (size_t)NT[t] * H;
        int g = (int)((n + TB - 1) / TB);
        if (g > 4096) g = 4096;
        copy_k<<<g, TB>>>(cur[t], x_in[t], n);
    }

    // 1. precompute WrSum / blSum for all layers
    {
        int n1 = N_LAYERS * 4 * H * H;
        wrsum_k<<<(n1 + TB - 1) / TB, TB>>>(Wr, WrSum);
        int n2 = N_LAYERS * 4 * H;
        blsum_k<<<(n2 + TB - 1) / TB, TB>>>(bl, blSum);
    }

    // 2. layers
    for (int l = 0; l < N_LAYERS; l++) {
        // acc_t = cur_t @ WrSum[l][t] + blSum[l][t]
        for (int t = 0; t < 4; t++) {
            int rows_per_block = TB / 32;
            int g = (NT[t] + rows_per_block - 1) / rows_per_block;
            gemm64_k<<<g, TB>>>(cur[t],
                                WrSum + ((size_t)l * 4 + t) * H * H,
                                blSum + ((size_t)l * 4 + t) * H,
                                acc[t], NT[t]);
        }
        // per relation: mean-aggregate transformed src feats into acc[dt]
        for (int r = 0; r < 9; r++) {
            int nd = NT[dt[r]];
            zero_k<<<(nd + TB - 1) / TB, TB>>>(cnt, nd);
            count_k<<<(E[r] + TB - 1) / TB, TB>>>(ei[r], E[r], cnt);
            inv_k<<<(nd + TB - 1) / TB, TB>>>(cnt, nd);

            int ns = NT[st[r]];
            int rows_per_block = TB / 32;
            int g = (ns + rows_per_block - 1) / rows_per_block;
            gemm64_k<<<g, TB>>>(cur[st[r]],
                                Wl + ((size_t)l * 9 + r) * H * H,
                                nullptr, y, ns);

            long long work = (long long)E[r] * 16;
            int gs = (int)((work + TB - 1) / TB);
            scatter_k<<<gs, TB>>>(ei[r], E[r], y, cnt, acc[dt[r]]);
        }
        // relu: cur = relu(acc)
        for (int t = 0; t < 4; t++) {
            size_t n = (size_t)NT[t] * H;
            int g = (int)((n + TB - 1) / TB);
            if (g > 4096) g = 4096;
            relu_k<<<g, TB>>>(cur[t], acc[t], n);
        }
    }

    // 3. head (cell only)
    {
        int rows_per_block = TB / 32;
        int g = (N_CELL + rows_per_block - 1) / rows_per_block;
        head_k<<<g, TB>>>(cur[3], projW, projb, outW, outb, (float*)d_out, N_CELL);
    }
}

// round 4
// speedup vs baseline: 3.4148x; 3.4148x over previous
#include <cuda_runtime.h>
#include <cstdint>
#include <cstddef>

// ---------------------------------------------------------------------------
// Problem constants
// ---------------------------------------------------------------------------
#define H 64
#define NL 3
#define N_ATOM  100000
#define N_BOND  200000
#define N_MOTIF 50000
#define N_CELL  5000
#define NTOT    355000   // packed rows: atom|bond|motif|cell

// Packed row offsets per node type
// atom 0, bond 100000, motif 300000, cell 350000

// agg layout: per dst type, rows have stride 64*nrel floats.
//   atom : 100000 rows x  64   off 0
//   bond : 200000 rows x 128   off 6,400,000
//   motif:  50000 rows x 192   off 32,000,000
//   cell :   5000 rows x 192   off 41,600,000
#define AGG_FLOATS 42560000

// cnt: concatenated per-relation dst-degree buffers (665000 floats)
#define CNT_FLOATS 665000

// stacked weights per layer: atom K=128, bond K=192, motif K=256, cell K=256
// per-layer floats = (128+192+256+256)*64 = 53248
#define WST_LAYER 53248

// ---------------------------------------------------------------------------
// Static scratch
// ---------------------------------------------------------------------------
__device__ __align__(16) float g_xbuf0[NTOT * H];
__device__ __align__(16) float g_xbuf1[NTOT * H];
__device__ __align__(16) float g_agg[AGG_FLOATS];
__device__ __align__(16) float g_cnt[CNT_FLOATS];
__device__ __align__(16) float g_Wst[NL * WST_LAYER];
__device__ __align__(16) float g_bsum[NL * 4 * H];

// ---------------------------------------------------------------------------
// Weight / bias stacking
//   Wstack(l,t) rows: [0,64)  = sum_r Wr[l][r]  over rels with dst t
//                     [64*(s+1), 64*(s+2)) = Wl[l][rel_list[t][s]]
// ---------------------------------------------------------------------------
__global__ void wstack_k(const float* __restrict__ Wr, const float* __restrict__ Wl,
                         float* __restrict__ Wst) {
    int i = blockIdx.x * blockDim.x + threadIdx.x;
    if (i >= NL * WST_LAYER) return;
    const int woff[5]     = {0, 8192, 20480, 36864, 53248};
    const int rcnt[4]     = {1, 2, 3, 3};
    const int rlist[4][3] = {{0,0,0},{1,3,0},{2,4,5},{6,7,8}};
    int l = i / WST_LAYER;
    int rem = i - l * WST_LAYER;
    int t = 0;
    while (rem >= woff[t + 1]) t++;
    int local = rem - woff[t];
    int krow = local >> 6;
    int col  = local & 63;
    float v;
    if (krow < 64) {
        v = 0.0f;
        for (int j = 0; j < rcnt[t]; j++)
            v += Wr[((size_t)(l * 9 + rlist[t][j]) * 64 + krow) * 64 + col];
    } else {
        int s = (krow >> 6) - 1;
        int r = rlist[t][s];
        int kk = krow & 63;
        v = Wl[((size_t)(l * 9 + r) * 64 + kk) * 64 + col];
    }
    Wst[i] = v;
}

__global__ void bsum_k(const float* __restrict__ bl, float* __restrict__ bsum) {
    int i = blockIdx.x * blockDim.x + threadIdx.x;
    if (i >= NL * 4 * H) return;
    const int rcnt[4]     = {1, 2, 3, 3};
    const int rlist[4][3] = {{0,0,0},{1,3,0},{2,4,5},{6,7,8}};
    int l = i / (4 * H);
    int rem = i - l * 4 * H;
    int t = rem >> 6;
    int col = rem & 63;
    float v = 0.0f;
    for (int j = 0; j < rcnt[t]; j++)
        v += bl[(size_t)(l * 9 + rlist[t][j]) * H + col];
    bsum[i] = v;
}

// ---------------------------------------------------------------------------
// Edge-path kernels (edge indices are int32; layout [2,E]: src then dst)
// ---------------------------------------------------------------------------
struct CntParams {
    const int* ei[9];
    int E[9];
    float* cnt[9];
};

__global__ void count_all_k(CntParams p) {
    int gsz = gridDim.x * blockDim.x;
    int t0  = blockIdx.x * blockDim.x + threadIdx.x;
    for (int r = 0; r < 9; r++) {
        const int* d = p.ei[r] + p.E[r];
        float* c = p.cnt[r];
        int E = p.E[r];
        for (int e = t0; e < E; e += gsz) atomicAdd(c + __ldg(d + e), 1.0f);
    }
}

__global__ void inv_all_k(float* __restrict__ cnt, int n) {
    int i = blockIdx.x * blockDim.x + threadIdx.x;
    if (i < n) cnt[i] = 1.0f / fmaxf(cnt[i], 1.0f);
}

struct EdgeParams {
    const int*   ei[9];
    int          E[9];
    const float* xs[9];    // src feature base (row 0) for this layer
    float*       agg[9];   // agg base pre-offset by slot*64
    int          stride[9];
};

// 16 threads per edge, float4 chunks; pure sum (mean scaling happens in GEMM)
__global__ void scatter_all_k(EdgeParams p) {
    long long gsz = (long long)gridDim.x * blockDim.x;
    long long t0  = (long long)blockIdx.x * blockDim.x + threadIdx.x;
    for (int r = 0; r < 9; r++) {
        const int* __restrict__ ei = p.ei[r];
        const float* __restrict__ xs = p.xs[r];
        float* agg = p.agg[r];
        int E = p.E[r];
        size_t stride = (size_t)p.stride[r];
        long long work = (long long)E * 16;
        for (long long g = t0; g < work; g += gsz) {
            int e = (int)(g >> 4);
            int c = (int)(g & 15);
            int src = __ldg(ei + e);
            int dst = __ldg(ei + E + e);
            float4 v = *(const float4*)(xs + (size_t)src * H + c * 4);
            float* pp = agg + (size_t)dst * stride + c * 4;
            asm volatile("red.global.add.v4.f32 [%0], {%1,%2,%3,%4};"
                         :: "l"(pp), "f"(v.x), "f"(v.y), "f"(v.z), "f"(v.w)
                         : "memory");
        }
    }
}

// ---------------------------------------------------------------------------
// Fused per-dst-type GEMM:
//   out = relu( [X | inv0*agg0 | inv1*agg1 | ...] @ Wstack + bias )
// 64-row tile per block, 256 threads, 4x4 micro-tile, K in chunks of 64.
// ---------------------------------------------------------------------------
__global__ void __launch_bounds__(256, 4)
gemm_fused_k(const float* __restrict__ X,
             const float* __restrict__ agg, int stride,
             const float* __restrict__ inv0,
             const float* __restrict__ inv1,
             const float* __restrict__ inv2,
             const float* __restrict__ Wst,
             const float* __restrict__ bias,
             float* __restrict__ out, int n, int nchunks) {
    __shared__ float Xs[64 * 64];
    __shared__ float Ws[64 * 64];
    const int tid = threadIdx.x;
    const int tx = tid & 15;        // output col group (4 cols)
    const int ty = tid >> 4;        // output row group (4 rows)
    const int row0 = blockIdx.x * 64;

    float acc[4][4];
#pragma unroll
    for (int i = 0; i < 4; i++)
#pragma unroll
        for (int j = 0; j < 4; j++) acc[i][j] = 0.0f;

    for (int c = 0; c < nchunks; c++) {
        const float* invp = (c == 1) ? inv0 : ((c == 2) ? inv1 : inv2);
        // load W chunk (4096 floats)
#pragma unroll
        for (int i = 0; i < 4; i++) {
            int idx = tid + i * 256;
            ((float4*)Ws)[idx] = ((const float4*)(Wst + c * 4096))[idx];
        }
        // load X chunk (64 rows x 64 cols)
#pragma unroll
        for (int i = 0; i < 4; i++) {
            int idx = tid + i * 256;
            int lr = idx >> 4;
            int c4 = idx & 15;
            int gr = row0 + lr;
            float4 v = make_float4(0.f, 0.f, 0.f, 0.f);
            if (gr < n) {
                if (c == 0) {
                    v = *(const float4*)(X + (size_t)gr * H + c4 * 4);
                } else {
                    v = *(const float4*)(agg + (size_t)gr * stride + (c - 1) * 64 + c4 * 4);
                    float s = __ldg(invp + gr);
                    v.x *= s; v.y *= s; v.z *= s; v.w *= s;
                }
            }
            ((float4*)Xs)[idx] = v;
        }
        __syncthreads();
#pragma unroll
        for (int k4 = 0; k4 < 16; k4++) {
            float4 xr[4];
#pragma unroll
            for (int i = 0; i < 4; i++)
                xr[i] = ((float4*)Xs)[(ty * 4 + i) * 16 + k4];
#pragma unroll
            for (int j = 0; j < 4; j++) {
                float4 w = ((float4*)Ws)[(k4 * 4 + j) * 16 + tx];
#pragma unroll
                for (int i = 0; i < 4; i++) {
                    float a = (&xr[i].x)[j];
                    acc[i][0] += a * w.x;
                    acc[i][1] += a * w.y;
                    acc[i][2] += a * w.z;
                    acc[i][3] += a * w.w;
                }
            }
        }
        __syncthreads();
    }
    float4 b = *(const float4*)(bias + tx * 4);
#pragma unroll
    for (int i = 0; i < 4; i++) {
        int gr = row0 + ty * 4 + i;
        if (gr < n) {
            float4 o;
            o.x = fmaxf(acc[i][0] + b.x, 0.f);
            o.y = fmaxf(acc[i][1] + b.y, 0.f);
            o.z = fmaxf(acc[i][2] + b.z, 0.f);
            o.w = fmaxf(acc[i][3] + b.w, 0.f);
            *(float4*)(out + (size_t)gr * H + tx * 4) = o;
        }
    }
}

// ---------------------------------------------------------------------------
// Head: out[row] = softplus(cell[row] @ projW + projb) @ outW + outb
// ---------------------------------------------------------------------------
__global__ void head_k(const float* __restrict__ X, const float* __restrict__ W,
                       const float* __restrict__ b, const float* __restrict__ ow,
                       const float* __restrict__ ob, float* __restrict__ out, int n) {
    __shared__ float Ws[H * H];
    for (int i = threadIdx.x; i < H * H; i += blockDim.x) Ws[i] = W[i];
    __syncthreads();

    int warp = threadIdx.x >> 5;
    int lane = threadIdx.x & 31;
    int row  = blockIdx.x * (blockDim.x >> 5) + warp;
    if (row >= n) return;

    const float* x = X + (size_t)row * H;
    float in_lo = x[lane];
    float in_hi = x[lane + 32];
    float a0 = b[lane];
    float a1 = b[lane + 32];

#pragma unroll
    for (int k = 0; k < 32; k++) {
        float a = __shfl_sync(0xffffffffu, in_lo, k);
        a0 += a * Ws[k * H + lane];
        a1 += a * Ws[k * H + lane + 32];
    }
#pragma unroll
    for (int k = 0; k < 32; k++) {
        float a = __shfl_sync(0xffffffffu, in_hi, k);
        a0 += a * Ws[(k + 32) * H + lane];
        a1 += a * Ws[(k + 32) * H + lane + 32];
    }
    a0 = fmaxf(a0, 0.0f) + log1pf(expf(-fabsf(a0)));
    a1 = fmaxf(a1, 0.0f) + log1pf(expf(-fabsf(a1)));
    float s = a0 * ow[lane] + a1 * ow[lane + 32];
#pragma unroll
    for (int o = 16; o > 0; o >>= 1) s += __shfl_down_sync(0xffffffffu, s, o);
    if (lane == 0) out[row] = s + ob[0];
}

// ---------------------------------------------------------------------------
// Host orchestration
// ---------------------------------------------------------------------------
extern "C" void kernel_launch(void* const* d_in, const int* in_sizes, int n_in,
                              void* d_out, int out_size) {
    const float* x_in[4] = {(const float*)d_in[0], (const float*)d_in[1],
                            (const float*)d_in[2], (const float*)d_in[3]};
    const float* Wl    = (const float*)d_in[4];
    const float* bl    = (const float*)d_in[5];
    const float* Wr    = (const float*)d_in[6];
    const float* projW = (const float*)d_in[7];
    const float* projb = (const float*)d_in[8];
    const float* outW  = (const float*)d_in[9];
    const float* outb  = (const float*)d_in[10];

    const int* ei[9];
    int E[9];
    for (int r = 0; r < 9; r++) {
        ei[r] = (const int*)d_in[11 + r];
        E[r]  = in_sizes[11 + r] / 2;
    }

    // Tables
    const int NT[4]    = {N_ATOM, N_BOND, N_MOTIF, N_CELL};
    const int ROFF[4]  = {0, 100000, 300000, 350000};          // packed row offsets
    const int st[9]    = {0, 0, 0, 1, 1, 2, 0, 1, 2};
    const int dt[9]    = {0, 1, 2, 1, 2, 2, 3, 3, 3};
    const int slot[9]  = {0, 0, 0, 1, 1, 2, 0, 1, 2};
    const size_t AOFF[4] = {0, 6400000, 32000000, 41600000};
    const int ASTRIDE[4] = {64, 128, 192, 192};
    const int WOFF[4]  = {0, 8192, 20480, 36864};
    const int NCHUNK[4]= {2, 3, 4, 4};
    const int CO[9]    = {0, 100000, 300000, 350000, 550000, 600000, 650000, 655000, 660000};

    float *buf0, *buf1, *agg, *cnt, *Wst, *bsum;
    cudaGetSymbolAddress((void**)&buf0, g_xbuf0);
    cudaGetSymbolAddress((void**)&buf1, g_xbuf1);
    cudaGetSymbolAddress((void**)&agg,  g_agg);
    cudaGetSymbolAddress((void**)&cnt,  g_cnt);
    cudaGetSymbolAddress((void**)&Wst,  g_Wst);
    cudaGetSymbolAddress((void**)&bsum, g_bsum);

    const int TB = 256;

    // 1. weight stacking (every call; deterministic)
    wstack_k<<<(NL * WST_LAYER + TB - 1) / TB, TB>>>(Wr, Wl, Wst);
    bsum_k<<<(NL * 4 * H + TB - 1) / TB, TB>>>(bl, bsum);

    // 2. per-relation dst degrees (layer-invariant): zero, count, invert
    cudaMemsetAsync(cnt, 0, CNT_FLOATS * sizeof(float));
    {
        CntParams cp;
        for (int r = 0; r < 9; r++) {
            cp.ei[r] = ei[r];
            cp.E[r]  = E[r];
            cp.cnt[r] = cnt + CO[r];
        }
        count_all_k<<<2048, TB>>>(cp);
        inv_all_k<<<(CNT_FLOATS + TB - 1) / TB, TB>>>(cnt, CNT_FLOATS);
    }

    // 3. layers
    for (int l = 0; l < NL; l++) {
        // x pointers for this layer (layer 0 reads harness inputs directly)
        const float* xcur[4];
        float* xnext = (l % 2 == 0) ? buf0 : buf1;
        const float* prev = (l % 2 == 0) ? buf1 : buf0;
        for (int t = 0; t < 4; t++)
            xcur[t] = (l == 0) ? x_in[t] : (prev + (size_t)ROFF[t] * H);

        // zero agg, then all 9 scatters in one kernel
        cudaMemsetAsync(agg, 0, AGG_FLOATS * sizeof(float));
        {
            EdgeParams ep;
            for (int r = 0; r < 9; r++) {
                ep.ei[r] = ei[r];
                ep.E[r]  = E[r];
                ep.xs[r] = xcur[st[r]];
                ep.agg[r] = agg + AOFF[dt[r]] + slot[r] * 64;
                ep.stride[r] = ASTRIDE[dt[r]];
            }
            scatter_all_k<<<8192, TB>>>(ep);
        }

        // fused GEMM per dst type
        for (int t = 0; t < 4; t++) {
            const float* i0 = cnt;  // defaults (unused slots never dereferenced
            const float* i1 = cnt;  //   beyond nchunks)
            const float* i2 = cnt;
            if (t == 0) { i0 = cnt + CO[0]; }
            if (t == 1) { i0 = cnt + CO[1]; i1 = cnt + CO[3]; }
            if (t == 2) { i0 = cnt + CO[2]; i1 = cnt + CO[4]; i2 = cnt + CO[5]; }
            if (t == 3) { i0 = cnt + CO[6]; i1 = cnt + CO[7]; i2 = cnt + CO[8]; }
            int g = (NT[t] + 63) / 64;
            gemm_fused_k<<<g, TB>>>(
                xcur[t],
                agg + AOFF[t], ASTRIDE[t],
                i0, i1, i2,
                Wst + (size_t)l * WST_LAYER + WOFF[t],
                bsum + (size_t)(l * 4 + t) * H,
                xnext + (size_t)ROFF[t] * H,
                NT[t], NCHUNK[t]);
        }
    }

    // 4. head on final cell features (layer 2 wrote buf0)
    {
        const float* xcell = buf0 + (size_t)ROFF[3] * H;
        int rows_per_block = TB / 32;
        int g = (N_CELL + rows_per_block - 1) / rows_per_block;
        head_k<<<g, TB>>>(xcell, projW, projb, outW, outb, (float*)d_out, N_CELL);
    }
}

// round 6
// speedup vs baseline: 3.6457x; 1.0676x over previous
#include <cuda_runtime.h>
#include <cstdint>
#include <cstddef>

// ---------------------------------------------------------------------------
// Problem constants
// ---------------------------------------------------------------------------
#define H 64
#define NL 3
#define N_ATOM  100000
#define N_BOND  200000
#define N_MOTIF 50000
#define N_CELL  5000
#define NTOT    355000

#define NCNT    665000            // sum of per-relation dst counts
#define NSCAN   665001            // +1 for total
#define MAXE    3000000           // csr_src capacity (actual 2.45M)
#define WST_LAYER 53248           // (128+192+256+256)*64

#define SCAN_TILE 1024
#define SCAN_NBLK ((NSCAN + SCAN_TILE - 1) / SCAN_TILE)   // 650

// ---------------------------------------------------------------------------
// Static scratch
// ---------------------------------------------------------------------------
__device__ __align__(16) float g_xbuf0[NTOT * H];
__device__ __align__(16) float g_xbuf1[NTOT * H];
__device__ __align__(16) int   g_cnt[NSCAN];
__device__ __align__(16) int   g_off[NSCAN];
__device__ __align__(16) int   g_cursor[NCNT];
__device__ __align__(16) int   g_bsums[SCAN_NBLK];
__device__ __align__(16) int   g_bscan[SCAN_NBLK];
__device__ __align__(16) int   g_csr[MAXE];
__device__ __align__(16) float g_Wst[NL * WST_LAYER];
__device__ __align__(16) float g_bsum[NL * 4 * H];

// Constant tables
__device__ __constant__ int c_CO[9]   = {0, 100000, 300000, 350000, 550000,
                                         600000, 650000, 655000, 660000};
__device__ __constant__ int c_SRCT[9] = {0, 0, 0, 1, 1, 2, 0, 1, 2};
__device__ __constant__ int c_RID[4][3] = {{0,0,0},{1,3,0},{2,4,5},{6,7,8}};
__device__ __constant__ int c_NT[4]   = {N_ATOM, N_BOND, N_MOTIF, N_CELL};
__device__ __constant__ int c_NCH[4]  = {2, 3, 4, 4};
__device__ __constant__ int c_WOFF[4] = {0, 8192, 20480, 36864};

// ---------------------------------------------------------------------------
// Weight / bias stacking
// ---------------------------------------------------------------------------
__global__ void wstack_k(const float* __restrict__ Wr, const float* __restrict__ Wl,
                         float* __restrict__ Wst) {
    int i = blockIdx.x * blockDim.x + threadIdx.x;
    if (i >= NL * WST_LAYER) return;
    const int woff[5]     = {0, 8192, 20480, 36864, 53248};
    const int rcnt[4]     = {1, 2, 3, 3};
    const int rlist[4][3] = {{0,0,0},{1,3,0},{2,4,5},{6,7,8}};
    int l = i / WST_LAYER;
    int rem = i - l * WST_LAYER;
    int t = 0;
    while (rem >= woff[t + 1]) t++;
    int local = rem - woff[t];
    int krow = local >> 6;
    int col  = local & 63;
    float v;
    if (krow < 64) {
        v = 0.0f;
        for (int j = 0; j < rcnt[t]; j++)
            v += Wr[((size_t)(l * 9 + rlist[t][j]) * 64 + krow) * 64 + col];
    } else {
        int s = (krow >> 6) - 1;
        int r = rlist[t][s];
        int kk = krow & 63;
        v = Wl[((size_t)(l * 9 + r) * 64 + kk) * 64 + col];
    }
    Wst[i] = v;
}

__global__ void bsum_k(const float* __restrict__ bl, float* __restrict__ bsum) {
    int i = blockIdx.x * blockDim.x + threadIdx.x;
    if (i >= NL * 4 * H) return;
    const int rcnt[4]     = {1, 2, 3, 3};
    const int rlist[4][3] = {{0,0,0},{1,3,0},{2,4,5},{6,7,8}};
    int l = i / (4 * H);
    int rem = i - l * 4 * H;
    int t = rem >> 6;
    int col = rem & 63;
    float v = 0.0f;
    for (int j = 0; j < rcnt[t]; j++)
        v += bl[(size_t)(l * 9 + rlist[t][j]) * H + col];
    bsum[i] = v;
}

// ---------------------------------------------------------------------------
// CSR build.  Edge indices are int32, layout [2,E]: src then dst.
// ---------------------------------------------------------------------------
struct EdgeP {
    const int* ei[9];
    int E[9];
};

__global__ void count_all_k(EdgeP p, int* __restrict__ cnt) {
    int gsz = gridDim.x * blockDim.x;
    int t0  = blockIdx.x * blockDim.x + threadIdx.x;
#pragma unroll
    for (int r = 0; r < 9; r++) {
        const int* d = p.ei[r] + p.E[r];
        int* c = cnt + c_CO[r];
        int E = p.E[r];
        for (int e = t0; e < E; e += gsz) atomicAdd(c + __ldg(d + e), 1);
    }
}

// scan pass 1: per-block (1024 elems) totals
__global__ void scan1_k(const int* __restrict__ in, int* __restrict__ bsums) {
    __shared__ int s[256];
    int b = blockIdx.x, tid = threadIdx.x;
    int base = b * SCAN_TILE + tid * 4;
    int t = 0;
#pragma unroll
    for (int j = 0; j < 4; j++) {
        int i = base + j;
        if (i < NSCAN) t += in[i];
    }
    s[tid] = t;
    __syncthreads();
    for (int d = 128; d > 0; d >>= 1) {
        if (tid < d) s[tid] += s[tid + d];
        __syncthreads();
    }
    if (tid == 0) bsums[b] = s[0];
}

// scan pass 2: single block exclusive scan over SCAN_NBLK block sums
__global__ void scan2_k(const int* __restrict__ bsums, int* __restrict__ bscan) {
    __shared__ int s[1024];
    int tid = threadIdx.x;
    s[tid] = (tid < SCAN_NBLK) ? bsums[tid] : 0;
    __syncthreads();
    for (int d = 1; d < 1024; d <<= 1) {
        int v = (tid >= d) ? s[tid - d] : 0;
        __syncthreads();
        s[tid] += v;
        __syncthreads();
    }
    if (tid < SCAN_NBLK) bscan[tid] = (tid == 0) ? 0 : s[tid - 1];
}

// scan pass 3: local exclusive scan + block base -> off
__global__ void scan3_k(const int* __restrict__ in, const int* __restrict__ bscan,
                        int* __restrict__ off) {
    __shared__ int s[256];
    int b = blockIdx.x, tid = threadIdx.x;
    int base = b * SCAN_TILE + tid * 4;
    int v[4];
    int t = 0;
#pragma unroll
    for (int j = 0; j < 4; j++) {
        int i = base + j;
        v[j] = (i < NSCAN) ? in[i] : 0;
        t += v[j];
    }
    s[tid] = t;
    __syncthreads();
    for (int d = 1; d < 256; d <<= 1) {
        int x = (tid >= d) ? s[tid - d] : 0;
        __syncthreads();
        s[tid] += x;
        __syncthreads();
    }
    int run = bscan[b] + s[tid] - t;   // exclusive prefix for this thread
#pragma unroll
    for (int j = 0; j < 4; j++) {
        int i = base + j;
        if (i < NSCAN) off[i] = run;
        run += v[j];
    }
}

__global__ void cursor_copy_k(const int* __restrict__ off, int* __restrict__ cur) {
    int i = blockIdx.x * blockDim.x + threadIdx.x;
    if (i < NCNT) cur[i] = off[i];
}

__global__ void fill_k(EdgeP p, int* __restrict__ cursor, int* __restrict__ csr) {
    int gsz = gridDim.x * blockDim.x;
    int t0  = blockIdx.x * blockDim.x + threadIdx.x;
#pragma unroll
    for (int r = 0; r < 9; r++) {
        const int* s = p.ei[r];
        const int* d = p.ei[r] + p.E[r];
        int* c = cursor + c_CO[r];
        int E = p.E[r];
        for (int e = t0; e < E; e += gsz) {
            int pos = atomicAdd(c + __ldg(d + e), 1);
            csr[pos] = __ldg(s + e);
        }
    }
}

// ---------------------------------------------------------------------------
// Fused layer kernel: for every dst type, every 64-row tile:
//   out = relu( [X | mean_gather(rel0) | mean_gather(rel1) | ...] @ Wstack + b )
// Gather reads neighbors via CSR directly into the Xs smem tile.
// Grid block -> (type, tile): atom 1563 | bond 3125 | motif 782 | cell 79.
// ---------------------------------------------------------------------------
#define GRID_GEMM 5549

struct GemmP {
    const float* x[4];    // current features per node type
    float* out[4];        // next features per node type
    const float* Wst;     // layer weight stack base
    const float* bsum;    // layer bias base (4*64)
    const int* off;
    const int* csr;
};

__global__ void __launch_bounds__(256, 4)
gemm_gather_k(GemmP p) {
    __shared__ float Xs[64 * 64];
    __shared__ float Ws[64 * 64];

    int b = blockIdx.x;
    int t, row0;
    if (b < 1563)      { t = 0; row0 = b * 64; }
    else if (b < 4688) { t = 1; row0 = (b - 1563) * 64; }
    else if (b < 5470) { t = 2; row0 = (b - 4688) * 64; }
    else               { t = 3; row0 = (b - 5470) * 64; }

    const int n       = c_NT[t];
    const int nchunks = c_NCH[t];
    const float* W0   = p.Wst + c_WOFF[t];
    const float* X    = p.x[t];

    const int tid  = threadIdx.x;
    const int tx   = tid & 15;
    const int ty   = tid >> 4;
    const int w    = tid >> 5;
    const int lane = tid & 31;

    float acc[4][4];
#pragma unroll
    for (int i = 0; i < 4; i++)
#pragma unroll
        for (int j = 0; j < 4; j++) acc[i][j] = 0.0f;

    for (int c = 0; c < nchunks; c++) {
        // --- load W chunk ---
#pragma unroll
        for (int i = 0; i < 4; i++) {
            int idx = tid + i * 256;
            ((float4*)Ws)[idx] = ((const float4*)(W0 + c * 4096))[idx];
        }
        // --- fill X chunk ---
        if (c == 0) {
#pragma unroll
            for (int i = 0; i < 4; i++) {
                int idx = tid + i * 256;
                int lr = idx >> 4;
                int c4 = idx & 15;
                int gr = row0 + lr;
                float4 v = make_float4(0.f, 0.f, 0.f, 0.f);
                if (gr < n) v = *(const float4*)(X + (size_t)gr * H + c4 * 4);
                ((float4*)Xs)[idx] = v;
            }
        } else {
            int rel = c_RID[t][c - 1];
            const float* __restrict__ xs = p.x[c_SRCT[rel]];
            const int* __restrict__ offr = p.off + c_CO[rel];
            const int* __restrict__ csr  = p.csr;
#pragma unroll 1
            for (int i = 0; i < 8; i++) {
                int lr = w * 8 + i;
                int gr = row0 + lr;
                float a0 = 0.f, a1 = 0.f;
                if (gr < n) {
                    int s = __ldg(offr + gr);
                    int e = __ldg(offr + gr + 1);
                    int k = s;
                    for (; k + 3 < e; k += 4) {
                        int s0 = __ldg(csr + k), s1 = __ldg(csr + k + 1);
                        int s2 = __ldg(csr + k + 2), s3 = __ldg(csr + k + 3);
                        const float* p0 = xs + (size_t)s0 * H;
                        const float* p1 = xs + (size_t)s1 * H;
                        const float* p2 = xs + (size_t)s2 * H;
                        const float* p3 = xs + (size_t)s3 * H;
                        float u0 = p0[lane], v0 = p0[lane + 32];
                        float u1 = p1[lane], v1 = p1[lane + 32];
                        float u2 = p2[lane], v2 = p2[lane + 32];
                        float u3 = p3[lane], v3 = p3[lane + 32];
                        a0 += (u0 + u1) + (u2 + u3);
                        a1 += (v0 + v1) + (v2 + v3);
                    }
                    for (; k < e; k++) {
                        int s0 = __ldg(csr + k);
                        const float* p0 = xs + (size_t)s0 * H;
                        a0 += p0[lane];
                        a1 += p0[lane + 32];
                    }
                    int deg = e - s;
                    float inv = 1.0f / (float)(deg > 1 ? deg : 1);
                    a0 *= inv; a1 *= inv;
                }
                Xs[lr * 64 + lane]      = a0;
                Xs[lr * 64 + lane + 32] = a1;
            }
        }
        __syncthreads();
        // --- FFMA ---
#pragma unroll
        for (int k4 = 0; k4 < 16; k4++) {
            float4 xr[4];
#pragma unroll
            for (int i = 0; i < 4; i++)
                xr[i] = ((float4*)Xs)[(ty * 4 + i) * 16 + k4];
#pragma unroll
            for (int j = 0; j < 4; j++) {
                float4 wv = ((float4*)Ws)[(k4 * 4 + j) * 16 + tx];
#pragma unroll
                for (int i = 0; i < 4; i++) {
                    float a = (&xr[i].x)[j];
                    acc[i][0] += a * wv.x;
                    acc[i][1] += a * wv.y;
                    acc[i][2] += a * wv.z;
                    acc[i][3] += a * wv.w;
                }
            }
        }
        __syncthreads();
    }

    float4 bb = *(const float4*)(p.bsum + t * 64 + tx * 4);
    float* out = p.out[t];
#pragma unroll
    for (int i = 0; i < 4; i++) {
        int gr = row0 + ty * 4 + i;
        if (gr < n) {
            float4 o;
            o.x = fmaxf(acc[i][0] + bb.x, 0.f);
            o.y = fmaxf(acc[i][1] + bb.y, 0.f);
            o.z = fmaxf(acc[i][2] + bb.z, 0.f);
            o.w = fmaxf(acc[i][3] + bb.w, 0.f);
            *(float4*)(out + (size_t)gr * H + tx * 4) = o;
        }
    }
}

// ---------------------------------------------------------------------------
// Head: out[row] = softplus(cell[row] @ projW + projb) @ outW + outb
// ---------------------------------------------------------------------------
__global__ void head_k(const float* __restrict__ X, const float* __restrict__ W,
                       const float* __restrict__ b, const float* __restrict__ ow,
                       const float* __restrict__ ob, float* __restrict__ out, int n) {
    __shared__ float Ws[H * H];
    for (int i = threadIdx.x; i < H * H; i += blockDim.x) Ws[i] = W[i];
    __syncthreads();

    int warp = threadIdx.x >> 5;
    int lane = threadIdx.x & 31;
    int row  = blockIdx.x * (blockDim.x >> 5) + warp;
    if (row >= n) return;

    const float* x = X + (size_t)row * H;
    float in_lo = x[lane];
    float in_hi = x[lane + 32];
    float a0 = b[lane];
    float a1 = b[lane + 32];

#pragma unroll
    for (int k = 0; k < 32; k++) {
        float a = __shfl_sync(0xffffffffu, in_lo, k);
        a0 += a * Ws[k * H + lane];
        a1 += a * Ws[k * H + lane + 32];
    }
#pragma unroll
    for (int k = 0; k < 32; k++) {
        float a = __shfl_sync(0xffffffffu, in_hi, k);
        a0 += a * Ws[(k + 32) * H + lane];
        a1 += a * Ws[(k + 32) * H + lane + 32];
    }
    a0 = fmaxf(a0, 0.0f) + log1pf(expf(-fabsf(a0)));
    a1 = fmaxf(a1, 0.0f) + log1pf(expf(-fabsf(a1)));
    float s = a0 * ow[lane] + a1 * ow[lane + 32];
#pragma unroll
    for (int o = 16; o > 0; o >>= 1) s += __shfl_down_sync(0xffffffffu, s, o);
    if (lane == 0) out[row] = s + ob[0];
}

// ---------------------------------------------------------------------------
// Host orchestration
// ---------------------------------------------------------------------------
extern "C" void kernel_launch(void* const* d_in, const int* in_sizes, int n_in,
                              void* d_out, int out_size) {
    const float* x_in[4] = {(const float*)d_in[0], (const float*)d_in[1],
                            (const float*)d_in[2], (const float*)d_in[3]};
    const float* Wl    = (const float*)d_in[4];
    const float* bl    = (const float*)d_in[5];
    const float* Wr    = (const float*)d_in[6];
    const float* projW = (const float*)d_in[7];
    const float* projb = (const float*)d_in[8];
    const float* outW  = (const float*)d_in[9];
    const float* outb  = (const float*)d_in[10];

    EdgeP ep;
    for (int r = 0; r < 9; r++) {
        ep.ei[r] = (const int*)d_in[11 + r];
        ep.E[r]  = in_sizes[11 + r] / 2;
    }

    const int ROFF[4] = {0, 100000, 300000, 350000};

    float *buf0, *buf1, *Wst, *bsum;
    int *cnt, *off, *cursor, *bsums, *bscan, *csr;
    cudaGetSymbolAddress((void**)&buf0,   g_xbuf0);
    cudaGetSymbolAddress((void**)&buf1,   g_xbuf1);
    cudaGetSymbolAddress((void**)&cnt,    g_cnt);
    cudaGetSymbolAddress((void**)&off,    g_off);
    cudaGetSymbolAddress((void**)&cursor, g_cursor);
    cudaGetSymbolAddress((void**)&bsums,  g_bsums);
    cudaGetSymbolAddress((void**)&bscan,  g_bscan);
    cudaGetSymbolAddress((void**)&csr,    g_csr);
    cudaGetSymbolAddress((void**)&Wst,    g_Wst);
    cudaGetSymbolAddress((void**)&bsum,   g_bsum);

    const int TB = 256;

    // 1. weight stacking
    wstack_k<<<(NL * WST_LAYER + TB - 1) / TB, TB>>>(Wr, Wl, Wst);
    bsum_k<<<(NL * 4 * H + TB - 1) / TB, TB>>>(bl, bsum);

    // 2. CSR build (once; shared across layers)
    cudaMemsetAsync(cnt, 0, NSCAN * sizeof(int));
    count_all_k<<<2048, TB>>>(ep, cnt);
    scan1_k<<<SCAN_NBLK, 256>>>(cnt, bsums);
    scan2_k<<<1, 1024>>>(bsums, bscan);
    scan3_k<<<SCAN_NBLK, 256>>>(cnt, bscan, off);
    cursor_copy_k<<<(NCNT + TB - 1) / TB, TB>>>(off, cursor);
    fill_k<<<2048, TB>>>(ep, cursor, csr);

    // 3. layers (fused gather + GEMM + relu, one launch per layer)
    for (int l = 0; l < NL; l++) {
        GemmP gp;
        float* xnext = (l % 2 == 0) ? buf0 : buf1;
        const float* prev = (l % 2 == 0) ? buf1 : buf0;
        for (int t = 0; t < 4; t++) {
            gp.x[t]   = (l == 0) ? x_in[t] : (prev + (size_t)ROFF[t] * H);
            gp.out[t] = xnext + (size_t)ROFF[t] * H;
        }
        gp.Wst  = Wst + (size_t)l * WST_LAYER;
        gp.bsum = bsum + (size_t)l * 4 * H;
        gp.off  = off;
        gp.csr  = csr;
        gemm_gather_k<<<GRID_GEMM, TB>>>(gp);
    }

    // 4. head on final cell features (layer 2 wrote buf0)
    {
        const float* xcell = buf0 + (size_t)ROFF[3] * H;
        int rows_per_block = TB / 32;
        int g = (N_CELL + rows_per_block - 1) / rows_per_block;
        head_k<<<g, TB>>>(xcell, projW, projb, outW, outb, (float*)d_out, N_CELL);
    }
}

// round 8
// speedup vs baseline: 3.9808x; 1.0919x over previous
#include <cuda_runtime.h>
#include <cstdint>
#include <cstddef>

// ---------------------------------------------------------------------------
// Problem constants
// ---------------------------------------------------------------------------
#define H 64
#define NL 3
#define N_ATOM  100000
#define N_BOND  200000
#define N_MOTIF 50000
#define N_CELL  5000
#define NTOT    355000

#define NCNT    665000
#define NSCAN   665001
#define MAXE    3000000
#define WST_LAYER 53248           // (128+192+256+256)*64

#define SCAN_TILE 1024
#define SCAN_NBLK ((NSCAN + SCAN_TILE - 1) / SCAN_TILE)   // 650

// ---------------------------------------------------------------------------
// Static scratch
// ---------------------------------------------------------------------------
__device__ __align__(16) float g_xbuf0[NTOT * H];
__device__ __align__(16) float g_xbuf1[NTOT * H];
__device__ __align__(16) int   g_cnt[NSCAN];
__device__ __align__(16) int   g_off[NSCAN];
__device__ __align__(16) int   g_cursor[NCNT];
__device__ __align__(16) int   g_bsums[SCAN_NBLK];
__device__ __align__(16) int   g_bscan[SCAN_NBLK];
__device__ __align__(16) int   g_csr[MAXE];
__device__ __align__(16) float g_Wst[NL * WST_LAYER];
__device__ __align__(16) float g_bsum[NL * 4 * H];

// Constant tables
__device__ __constant__ int c_CO[9]   = {0, 100000, 300000, 350000, 550000,
                                         600000, 650000, 655000, 660000};
__device__ __constant__ int c_SRCT[9] = {0, 0, 0, 1, 1, 2, 0, 1, 2};
__device__ __constant__ int c_RID[4][3] = {{0,0,0},{1,3,0},{2,4,5},{6,7,8}};
__device__ __constant__ int c_NT[4]   = {N_ATOM, N_BOND, N_MOTIF, N_CELL};
__device__ __constant__ int c_NCH[4]  = {2, 3, 4, 4};
__device__ __constant__ int c_WOFF[4] = {0, 8192, 20480, 36864};

// ---------------------------------------------------------------------------
// Packed fp32x2 helpers (sm_103a; ptxas never emits these from C++)
// ---------------------------------------------------------------------------
__device__ __forceinline__ void ffma2(unsigned long long& acc,
                                      unsigned long long a,
                                      unsigned long long b) {
    asm("fma.rn.f32x2 %0, %1, %2, %0;" : "+l"(acc) : "l"(a), "l"(b));
}
__device__ __forceinline__ void fadd2(unsigned long long& acc,
                                      unsigned long long v) {
    asm("add.rn.f32x2 %0, %1, %0;" : "+l"(acc) : "l"(v));
}
__device__ __forceinline__ void fmul2(unsigned long long& acc,
                                      unsigned long long v) {
    asm("mul.rn.f32x2 %0, %1, %0;" : "+l"(acc) : "l"(v));
}
__device__ __forceinline__ unsigned long long pack2(float a) {
    unsigned long long d;
    asm("mov.b64 %0, {%1, %1};" : "=l"(d) : "f"(a));
    return d;
}

// ---------------------------------------------------------------------------
// Weight / bias stacking
// ---------------------------------------------------------------------------
__global__ void wstack_k(const float* __restrict__ Wr, const float* __restrict__ Wl,
                         float* __restrict__ Wst) {
    int i = blockIdx.x * blockDim.x + threadIdx.x;
    if (i >= NL * WST_LAYER) return;
    const int woff[5]     = {0, 8192, 20480, 36864, 53248};
    const int rcnt[4]     = {1, 2, 3, 3};
    const int rlist[4][3] = {{0,0,0},{1,3,0},{2,4,5},{6,7,8}};
    int l = i / WST_LAYER;
    int rem = i - l * WST_LAYER;
    int t = 0;
    while (rem >= woff[t + 1]) t++;
    int local = rem - woff[t];
    int krow = local >> 6;
    int col  = local & 63;
    float v;
    if (krow < 64) {
        v = 0.0f;
        for (int j = 0; j < rcnt[t]; j++)
            v += Wr[((size_t)(l * 9 + rlist[t][j]) * 64 + krow) * 64 + col];
    } else {
        int s = (krow >> 6) - 1;
        int r = rlist[t][s];
        int kk = krow & 63;
        v = Wl[((size_t)(l * 9 + r) * 64 + kk) * 64 + col];
    }
    Wst[i] = v;
}

__global__ void bsum_k(const float* __restrict__ bl, float* __restrict__ bsum) {
    int i = blockIdx.x * blockDim.x + threadIdx.x;
    if (i >= NL * 4 * H) return;
    const int rcnt[4]     = {1, 2, 3, 3};
    const int rlist[4][3] = {{0,0,0},{1,3,0},{2,4,5},{6,7,8}};
    int l = i / (4 * H);
    int rem = i - l * 4 * H;
    int t = rem >> 6;
    int col = rem & 63;
    float v = 0.0f;
    for (int j = 0; j < rcnt[t]; j++)
        v += bl[(size_t)(l * 9 + rlist[t][j]) * H + col];
    bsum[i] = v;
}

// ---------------------------------------------------------------------------
// CSR build.  Edge indices are int32, layout [2,E]: src then dst.
// ---------------------------------------------------------------------------
struct EdgeP {
    const int* ei[9];
    int E[9];
};

__global__ void count_all_k(EdgeP p, int* __restrict__ cnt) {
    int gsz = gridDim.x * blockDim.x;
    int t0  = blockIdx.x * blockDim.x + threadIdx.x;
#pragma unroll
    for (int r = 0; r < 9; r++) {
        const int* d = p.ei[r] + p.E[r];
        int* c = cnt + c_CO[r];
        int E = p.E[r];
        for (int e = t0; e < E; e += gsz) atomicAdd(c + __ldg(d + e), 1);
    }
}

__global__ void scan1_k(const int* __restrict__ in, int* __restrict__ bsums) {
    __shared__ int s[256];
    int b = blockIdx.x, tid = threadIdx.x;
    int base = b * SCAN_TILE + tid * 4;
    int t = 0;
#pragma unroll
    for (int j = 0; j < 4; j++) {
        int i = base + j;
        if (i < NSCAN) t += in[i];
    }
    s[tid] = t;
    __syncthreads();
    for (int d = 128; d > 0; d >>= 1) {
        if (tid < d) s[tid] += s[tid + d];
        __syncthreads();
    }
    if (tid == 0) bsums[b] = s[0];
}

__global__ void scan2_k(const int* __restrict__ bsums, int* __restrict__ bscan) {
    __shared__ int s[1024];
    int tid = threadIdx.x;
    s[tid] = (tid < SCAN_NBLK) ? bsums[tid] : 0;
    __syncthreads();
    for (int d = 1; d < 1024; d <<= 1) {
        int v = (tid >= d) ? s[tid - d] : 0;
        __syncthreads();
        s[tid] += v;
        __syncthreads();
    }
    if (tid < SCAN_NBLK) bscan[tid] = (tid == 0) ? 0 : s[tid - 1];
}

__global__ void scan3_k(const int* __restrict__ in, const int* __restrict__ bscan,
                        int* __restrict__ off) {
    __shared__ int s[256];
    int b = blockIdx.x, tid = threadIdx.x;
    int base = b * SCAN_TILE + tid * 4;
    int v[4];
    int t = 0;
#pragma unroll
    for (int j = 0; j < 4; j++) {
        int i = base + j;
        v[j] = (i < NSCAN) ? in[i] : 0;
        t += v[j];
    }
    s[tid] = t;
    __syncthreads();
    for (int d = 1; d < 256; d <<= 1) {
        int x = (tid >= d) ? s[tid - d] : 0;
        __syncthreads();
        s[tid] += x;
        __syncthreads();
    }
    int run = bscan[b] + s[tid] - t;
#pragma unroll
    for (int j = 0; j < 4; j++) {
        int i = base + j;
        if (i < NSCAN) off[i] = run;
        run += v[j];
    }
}

__global__ void cursor_copy_k(const int* __restrict__ off, int* __restrict__ cur) {
    int i = blockIdx.x * blockDim.x + threadIdx.x;
    if (i < NCNT) cur[i] = off[i];
}

__global__ void fill_k(EdgeP p, int* __restrict__ cursor, int* __restrict__ csr) {
    int gsz = gridDim.x * blockDim.x;
    int t0  = blockIdx.x * blockDim.x + threadIdx.x;
#pragma unroll
    for (int r = 0; r < 9; r++) {
        const int* s = p.ei[r];
        const int* d = p.ei[r] + p.E[r];
        int* c = cursor + c_CO[r];
        int E = p.E[r];
        for (int e = t0; e < E; e += gsz) {
            int pos = atomicAdd(c + __ldg(d + e), 1);
            csr[pos] = __ldg(s + e);
        }
    }
}

// ---------------------------------------------------------------------------
// Fused layer kernel with f32x2 packed math.
// Grid block -> (type, tile): atom 1563 | bond 3125 | motif 782 | cell 79.
// ---------------------------------------------------------------------------
#define GRID_GEMM 5549

struct GemmP {
    const float* x[4];
    float* out[4];
    const float* Wst;
    const float* bsum;
    const int* off;
    const int* csr;
};

__global__ void __launch_bounds__(256, 4)
gemm_gather_k(GemmP p) {
    __shared__ __align__(16) float Xs[64 * 64];
    __shared__ __align__(16) float Ws[64 * 64];

    int b = blockIdx.x;
    int t, row0;
    if (b < 1563)      { t = 0; row0 = b * 64; }
    else if (b < 4688) { t = 1; row0 = (b - 1563) * 64; }
    else if (b < 5470) { t = 2; row0 = (b - 4688) * 64; }
    else               { t = 3; row0 = (b - 5470) * 64; }

    const int n       = c_NT[t];
    const int nchunks = c_NCH[t];
    const float* W0   = p.Wst + c_WOFF[t];
    const float* X    = p.x[t];

    const int tid  = threadIdx.x;
    const int tx   = tid & 15;
    const int ty   = tid >> 4;
    const int w    = tid >> 5;
    const int lane = tid & 31;

    // packed accumulators: acc01[i] = cols (4tx, 4tx+1), acc23[i] = (4tx+2, 4tx+3)
    unsigned long long acc01[4], acc23[4];
#pragma unroll
    for (int i = 0; i < 4; i++) { acc01[i] = 0ull; acc23[i] = 0ull; }

    for (int c = 0; c < nchunks; c++) {
        // --- load W chunk (4096 floats) ---
#pragma unroll
        for (int i = 0; i < 4; i++) {
            int idx = tid + i * 256;
            ((float4*)Ws)[idx] = ((const float4*)(W0 + c * 4096))[idx];
        }
        // --- fill X chunk ---
        if (c == 0) {
#pragma unroll
            for (int i = 0; i < 4; i++) {
                int idx = tid + i * 256;
                int lr = idx >> 4;
                int c4 = idx & 15;
                int gr = row0 + lr;
                float4 v = make_float4(0.f, 0.f, 0.f, 0.f);
                if (gr < n) v = *(const float4*)(X + (size_t)gr * H + c4 * 4);
                ((float4*)Xs)[idx] = v;
            }
        } else {
            int rel = c_RID[t][c - 1];
            const unsigned long long* __restrict__ xs2 =
                (const unsigned long long*)p.x[c_SRCT[rel]];   // row = 32 u64
            const int* __restrict__ offr = p.off + c_CO[rel];
            const int* __restrict__ csr  = p.csr;
#pragma unroll 1
            for (int i = 0; i < 8; i++) {
                int lr = w * 8 + i;
                int gr = row0 + lr;
                unsigned long long a = 0ull;
                if (gr < n) {
                    int s = __ldg(offr + gr);
                    int e = __ldg(offr + gr + 1);
                    int k = s;
                    for (; k + 7 < e; k += 8) {
                        int i0 = __ldg(csr + k),     i1 = __ldg(csr + k + 1);
                        int i2 = __ldg(csr + k + 2), i3 = __ldg(csr + k + 3);
                        int i4 = __ldg(csr + k + 4), i5 = __ldg(csr + k + 5);
                        int i6 = __ldg(csr + k + 6), i7 = __ldg(csr + k + 7);
                        unsigned long long v0 = __ldg(xs2 + (size_t)i0 * 32 + lane);
                        unsigned long long v1 = __ldg(xs2 + (size_t)i1 * 32 + lane);
                        unsigned long long v2 = __ldg(xs2 + (size_t)i2 * 32 + lane);
                        unsigned long long v3 = __ldg(xs2 + (size_t)i3 * 32 + lane);
                        unsigned long long v4 = __ldg(xs2 + (size_t)i4 * 32 + lane);
                        unsigned long long v5 = __ldg(xs2 + (size_t)i5 * 32 + lane);
                        unsigned long long v6 = __ldg(xs2 + (size_t)i6 * 32 + lane);
                        unsigned long long v7 = __ldg(xs2 + (size_t)i7 * 32 + lane);
                        fadd2(v0, v1); fadd2(v2, v3);
                        fadd2(v4, v5); fadd2(v6, v7);
                        fadd2(v0, v2); fadd2(v4, v6);
                        fadd2(v0, v4);
                        fadd2(a, v0);
                    }
                    for (; k + 3 < e; k += 4) {
                        int i0 = __ldg(csr + k),     i1 = __ldg(csr + k + 1);
                        int i2 = __ldg(csr + k + 2), i3 = __ldg(csr + k + 3);
                        unsigned long long v0 = __ldg(xs2 + (size_t)i0 * 32 + lane);
                        unsigned long long v1 = __ldg(xs2 + (size_t)i1 * 32 + lane);
                        unsigned long long v2 = __ldg(xs2 + (size_t)i2 * 32 + lane);
                        unsigned long long v3 = __ldg(xs2 + (size_t)i3 * 32 + lane);
                        fadd2(v0, v1); fadd2(v2, v3);
                        fadd2(v0, v2);
                        fadd2(a, v0);
                    }
                    for (; k < e; k++) {
                        int i0 = __ldg(csr + k);
                        unsigned long long v0 = __ldg(xs2 + (size_t)i0 * 32 + lane);
                        fadd2(a, v0);
                    }
                    int deg = e - s;
                    float inv = 1.0f / (float)(deg > 1 ? deg : 1);
                    fmul2(a, pack2(inv));
                }
                ((unsigned long long*)(Xs + lr * 64))[lane] = a;
            }
        }
        __syncthreads();
        // --- packed FFMA ---
#pragma unroll
        for (int k4 = 0; k4 < 16; k4++) {
            float4 xr[4];
#pragma unroll
            for (int i = 0; i < 4; i++)
                xr[i] = ((float4*)Xs)[(ty * 4 + i) * 16 + k4];
#pragma unroll
            for (int j = 0; j < 4; j++) {
                ulonglong2 wv = ((ulonglong2*)Ws)[(k4 * 4 + j) * 16 + tx];
#pragma unroll
                for (int i = 0; i < 4; i++) {
                    unsigned long long aa = pack2((&xr[i].x)[j]);
                    ffma2(acc01[i], aa, wv.x);
                    ffma2(acc23[i], aa, wv.y);
                }
            }
        }
        __syncthreads();
    }

    float4 bb = *(const float4*)(p.bsum + t * 64 + tx * 4);
    float* out = p.out[t];
#pragma unroll
    for (int i = 0; i < 4; i++) {
        int gr = row0 + ty * 4 + i;
        if (gr < n) {
            float2 lo = *(float2*)&acc01[i];
            float2 hi = *(float2*)&acc23[i];
            float4 o;
            o.x = fmaxf(lo.x + bb.x, 0.f);
            o.y = fmaxf(lo.y + bb.y, 0.f);
            o.z = fmaxf(hi.x + bb.z, 0.f);
            o.w = fmaxf(hi.y + bb.w, 0.f);
            *(float4*)(out + (size_t)gr * H + tx * 4) = o;
        }
    }
}

// ---------------------------------------------------------------------------
// Head: out[row] = softplus(cell[row] @ projW + projb) @ outW + outb
// ---------------------------------------------------------------------------
__global__ void head_k(const float* __restrict__ X, const float* __restrict__ W,
                       const float* __restrict__ b, const float* __restrict__ ow,
                       const float* __restrict__ ob, float* __restrict__ out, int n) {
    __shared__ float Ws[H * H];
    for (int i = threadIdx.x; i < H * H; i += blockDim.x) Ws[i] = W[i];
    __syncthreads();

    int warp = threadIdx.x >> 5;
    int lane = threadIdx.x & 31;
    int row  = blockIdx.x * (blockDim.x >> 5) + warp;
    if (row >= n) return;

    const float* x = X + (size_t)row * H;
    float in_lo = x[lane];
    float in_hi = x[lane + 32];
    float a0 = b[lane];
    float a1 = b[lane + 32];

#pragma unroll
    for (int k = 0; k < 32; k++) {
        float a = __shfl_sync(0xffffffffu, in_lo, k);
        a0 += a * Ws[k * H + lane];
        a1 += a * Ws[k * H + lane + 32];
    }
#pragma unroll
    for (int k = 0; k < 32; k++) {
        float a = __shfl_sync(0xffffffffu, in_hi, k);
        a0 += a * Ws[(k + 32) * H + lane];
        a1 += a * Ws[(k + 32) * H + lane + 32];
    }
    a0 = fmaxf(a0, 0.0f) + log1pf(expf(-fabsf(a0)));
    a1 = fmaxf(a1, 0.0f) + log1pf(expf(-fabsf(a1)));
    float s = a0 * ow[lane] + a1 * ow[lane + 32];
#pragma unroll
    for (int o = 16; o > 0; o >>= 1) s += __shfl_down_sync(0xffffffffu, s, o);
    if (lane == 0) out[row] = s + ob[0];
}

// ---------------------------------------------------------------------------
// Host orchestration
// ---------------------------------------------------------------------------
extern "C" void kernel_launch(void* const* d_in, const int* in_sizes, int n_in,
                              void* d_out, int out_size) {
    const float* x_in[4] = {(const float*)d_in[0], (const float*)d_in[1],
                            (const float*)d_in[2], (const float*)d_in[3]};
    const float* Wl    = (const float*)d_in[4];
    const float* bl    = (const float*)d_in[5];
    const float* Wr    = (const float*)d_in[6];
    const float* projW = (const float*)d_in[7];
    const float* projb = (const float*)d_in[8];
    const float* outW  = (const float*)d_in[9];
    const float* outb  = (const float*)d_in[10];

    EdgeP ep;
    for (int r = 0; r < 9; r++) {
        ep.ei[r] = (const int*)d_in[11 + r];
        ep.E[r]  = in_sizes[11 + r] / 2;
    }

    const int ROFF[4] = {0, 100000, 300000, 350000};

    float *buf0, *buf1, *Wst, *bsum;
    int *cnt, *off, *cursor, *bsums, *bscan, *csr;
    cudaGetSymbolAddress((void**)&buf0,   g_xbuf0);
    cudaGetSymbolAddress((void**)&buf1,   g_xbuf1);
    cudaGetSymbolAddress((void**)&cnt,    g_cnt);
    cudaGetSymbolAddress((void**)&off,    g_off);
    cudaGetSymbolAddress((void**)&cursor, g_cursor);
    cudaGetSymbolAddress((void**)&bsums,  g_bsums);
    cudaGetSymbolAddress((void**)&bscan,  g_bscan);
    cudaGetSymbolAddress((void**)&csr,    g_csr);
    cudaGetSymbolAddress((void**)&Wst,    g_Wst);
    cudaGetSymbolAddress((void**)&bsum,   g_bsum);

    const int TB = 256;

    // 1. weight stacking
    wstack_k<<<(NL * WST_LAYER + TB - 1) / TB, TB>>>(Wr, Wl, Wst);
    bsum_k<<<(NL * 4 * H + TB - 1) / TB, TB>>>(bl, bsum);

    // 2. CSR build (once; shared across layers)
    cudaMemsetAsync(cnt, 0, NSCAN * sizeof(int));
    count_all_k<<<2048, TB>>>(ep, cnt);
    scan1_k<<<SCAN_NBLK, 256>>>(cnt, bsums);
    scan2_k<<<1, 1024>>>(bsums, bscan);
    scan3_k<<<SCAN_NBLK, 256>>>(cnt, bscan, off);
    cursor_copy_k<<<(NCNT + TB - 1) / TB, TB>>>(off, cursor);
    fill_k<<<2048, TB>>>(ep, cursor, csr);

    // 3. layers
    for (int l = 0; l < NL; l++) {
        GemmP gp;
        float* xnext = (l % 2 == 0) ? buf0 : buf1;
        const float* prev = (l % 2 == 0) ? buf1 : buf0;
        for (int t = 0; t < 4; t++) {
            gp.x[t]   = (l == 0) ? x_in[t] : (prev + (size_t)ROFF[t] * H);
            gp.out[t] = xnext + (size_t)ROFF[t] * H;
        }
        gp.Wst  = Wst + (size_t)l * WST_LAYER;
        gp.bsum = bsum + (size_t)l * 4 * H;
        gp.off  = off;
        gp.csr  = csr;
        gemm_gather_k<<<GRID_GEMM, TB>>>(gp);
    }

    // 4. head
    {
        const float* xcell = buf0 + (size_t)ROFF[3] * H;
        int rows_per_block = TB / 32;
        int g = (N_CELL + rows_per_block - 1) / rows_per_block;
        head_k<<<g, TB>>>(xcell, projW, projb, outW, outb, (float*)d_out, N_CELL);
    }
}